// round 11
// baseline (speedup 1.0000x reference)
#include <cuda_runtime.h>
#include <cuda_fp16.h>
#include <cstdint>

// Problem constants
#define C_IN   128
#define D_OUT  256
#define IMG    64
#define R1     8
#define R2     4
#define TH     2           // output rows per CTA (M = 2*64 = 128)
#define ND     128         // output channels per CTA (N tile)
#define NG     12          // 4 c-chunks * 3 kh-groups

// SMEM word-layout (uint32 = half2 words)
#define SLAB_STRIDE  20                // 16 data words + 4 pad (ldmatrix conflict-free)
#define SLAB_POS     264               // 4 rows * 66 cols (halo cols 0 and 65)
#define SLAB_WORDS   (SLAB_POS * SLAB_STRIDE)      // 5280
#define B_TAP_WORDS  2048              // 2 ks * 128 d * 8 words
#define B_GRP_WORDS  (3 * B_TAP_WORDS)             // 6144 (3 kw taps)
#define SM_B         SLAB_WORDS
#define SM_TOTALW    (SM_B + 3 * B_GRP_WORDS)      // 23712 words = 94848 B

// fp16 weights, fragment-ready (wB pair-interleaved, unchanged from R8):
//   word idx = (((tap*4+cc)*2+ks)*256 + d)*8 + wB,  wB=(c16&7)+(c16>>3), c16=c&15
__device__ uint32_t g_Wp[9 * 4 * 2 * 256 * 8];
// fp16 x, PLAIN channel order (ldmatrix distributes fragments):
//   word idx = (((n*4+cc)*64+h)*64+w)*16 + i  with word i = channels (2i, 2i+1) of chunk
__device__ uint32_t g_xh[32 * 4 * 64 * 64 * 16];   // 33.5 MB

__device__ __forceinline__ void mma_f16(float* d, const uint32_t* a, const uint32_t* b) {
    asm volatile(
        "mma.sync.aligned.m16n8k16.row.col.f32.f16.f16.f32 "
        "{%0,%1,%2,%3}, {%4,%5,%6,%7}, {%8,%9}, {%0,%1,%2,%3};"
        : "+f"(d[0]), "+f"(d[1]), "+f"(d[2]), "+f"(d[3])
        : "r"(a[0]), "r"(a[1]), "r"(a[2]), "r"(a[3]), "r"(b[0]), "r"(b[1]));
}
__device__ __forceinline__ void ldsm_x4(uint32_t* r, uint32_t addr) {
    asm volatile("ldmatrix.sync.aligned.m8n8.x4.shared.b16 {%0,%1,%2,%3}, [%4];"
        : "=r"(r[0]), "=r"(r[1]), "=r"(r[2]), "=r"(r[3]) : "r"(addr));
}
__device__ __forceinline__ void cp_async16(uint32_t saddr, const void* gptr) {
    asm volatile("cp.async.ca.shared.global [%0], [%1], 16;" :: "r"(saddr), "l"(gptr));
}

// ---------------------------------------------------------------------------
// Phase 1a: rebuild W (full fp32 math), pack fp16 pairs into g_Wp (R8 layout)
// ---------------------------------------------------------------------------
__global__ void build_w_kernel(const float* __restrict__ core0,
                               const float* __restrict__ core1,
                               const float* __restrict__ core2) {
    const int d = blockIdx.x;
    const int t = threadIdx.x;           // 128 threads = channels
    __shared__ float M[R1 * 9];
    if (t < R1 * 9) {
        const int r = t / 9, kj = t % 9, kh = kj / 3, kw = kj % 3;
        float acc = 0.f;
        #pragma unroll
        for (int s = 0; s < R2; s++)
            acc += core1[((d * R1 + r) * 3 + kh) * R2 + s] * core2[(d * R2 + s) * 3 + kw];
        M[t] = acc;
    }
    __syncthreads();
    const int c = t;
    float a[R1];
    #pragma unroll
    for (int r = 0; r < R1; r++) a[r] = core0[(d * C_IN + c) * R1 + r];
    #pragma unroll
    for (int kj = 0; kj < 9; kj++) {
        float acc = 0.f;
        #pragma unroll
        for (int r = 0; r < R1; r++) acc += a[r] * M[r * 9 + kj];
        const float hiv = __shfl_down_sync(0xffffffffu, acc, 1);
        if (!(c & 1)) {
            const int cc = c >> 5, cl = c & 31;
            const int ks = cl >> 4, c16 = cl & 15;
            const int wB = (c16 & 7) + (c16 >> 3);
            __half2 h2 = __floats2half2_rn(acc, hiv);
            g_Wp[((((kj * 4 + cc) * 2 + ks) * 256) + d) * 8 + wB] =
                *reinterpret_cast<uint32_t*>(&h2);
        }
    }
}

// ---------------------------------------------------------------------------
// Phase 1b: convert x -> fp16, PLAIN channel-pair words
// ---------------------------------------------------------------------------
__global__ __launch_bounds__(256)
void prepack_x_kernel(const float* __restrict__ x) {
    const int ncc = blockIdx.x;          // n*4+cc
    const int h   = blockIdx.y;
    const int n   = ncc >> 2;
    const int cc  = ncc & 3;
    const int tid = threadIdx.x;
    __shared__ float xs[32][65];

    for (int i = tid; i < 32 * 64; i += 256) {
        const int c = i >> 6, w = i & 63;
        xs[c][w] = x[((n * C_IN + cc * 32 + c) * IMG + h) * IMG + w];
    }
    __syncthreads();

    uint32_t* dst = g_xh + ((size_t)(ncc * 64 + h) * 64) * 16;
    for (int i = tid; i < 64 * 16; i += 256) {
        const int w = i >> 4, sw = i & 15;
        __half2 h2 = __floats2half2_rn(xs[2 * sw][w], xs[2 * sw + 1][w]);
        dst[w * 16 + sw] = *reinterpret_cast<uint32_t*>(&h2);
    }
}

// ---------------------------------------------------------------------------
// Phase 2: fp16 m16n8k16 implicit GEMM, kh-group pipeline + ldmatrix a-frags.
// CTA: M=128 x N=128. 8 warps = 2(M-row) x 4(N); warp 64x32.
// Loop: 12 groups (cc x kh); group = 3 kw taps x 2 ksteps(K=16).
// B per-group triple-buffered (depth 2); slab single-buffered, restaged at cc
// boundaries. One __syncthreads + one wait_group per group.
// ---------------------------------------------------------------------------
__global__ __launch_bounds__(256, 2)
void conv_mma_kernel(const float* __restrict__ bias, float* __restrict__ out) {
    extern __shared__ uint32_t smw[];
    const int tid = threadIdx.x;
    const int wid = tid >> 5;
    const int lane = tid & 31;
    const int g = lane >> 2;
    const int q = lane & 3;
    const int warp_m = wid & 1;
    const int warp_n = wid >> 1;
    const int ny = blockIdx.y;
    const int n  = blockIdx.z;
    const int h0 = blockIdx.x * TH;

    uint32_t smem_base;
    asm("{ .reg .u64 t; cvta.to.shared.u64 t, %1; cvt.u32.u64 %0, t; }"
        : "=r"(smem_base) : "l"((void*)smw));

    float acc[4][4][4];
    #pragma unroll
    for (int i = 0; i < 4; i++)
        #pragma unroll
        for (int j = 0; j < 4; j++)
            #pragma unroll
            for (int k = 0; k < 4; k++) acc[i][j][k] = 0.f;

    auto issue_slab = [&](int cc) {
        const uint32_t* gsrc = g_xh + ((size_t)(n * 4 + cc) * 64) * 64 * 16;
        #pragma unroll
        for (int t = 0; t < 4; t++) {
            const int i = tid + t * 256;      // 0..1023
            const int r = i >> 8, rem = i & 255;
            const int w = rem >> 2, cq = rem & 3;
            const int h = h0 - 1 + r;
            if ((unsigned)h < (unsigned)IMG)
                cp_async16(smem_base + (((r * 66 + 1 + w) * SLAB_STRIDE) + cq * 4) * 4,
                           gsrc + ((size_t)h * 64 + w) * 16 + cq * 4);
        }
    };
    auto issue_Bgrp = [&](int gi) {
        const int cc = gi / 3, kh = gi % 3, buf = gi % 3;
        const uint32_t sbase = smem_base + (SM_B + buf * B_GRP_WORDS) * 4;
        #pragma unroll
        for (int t = 0; t < 6; t++) {
            const int i = tid + t * 256;      // 0..1535
            const int t3 = i >> 9, rem = i & 511;
            const int ks = rem >> 8, ci = rem & 255;
            const uint32_t* gsrc =
                g_Wp + (size_t)((3 * kh + t3) * 4 + cc) * 4096 + ny * 1024;
            cp_async16(sbase + (t3 * 2048 + ks * 1024 + ci * 4) * 4,
                       gsrc + ks * 2048 + ci * 4);
        }
    };

    // ---- prologue: zero slab (halo stays zero), stage slab(0), B(0), B(1) ----
    for (int i = tid; i < SLAB_WORDS; i += 256) smw[i] = 0;
    __syncthreads();
    issue_slab(0);
    issue_Bgrp(0);
    asm volatile("cp.async.commit_group;" ::: "memory");
    issue_Bgrp(1);
    asm volatile("cp.async.commit_group;" ::: "memory");

    // per-thread ldmatrix row base: row-within-16 = lane&15, k-half word = +4 if lane>=16
    const uint32_t a_thr_off = (uint32_t)((lane & 15) * SLAB_STRIDE + ((lane >> 2) & 4)) * 4;

    for (int gi = 0; gi < NG; gi++) {
        const int cc = gi / 3;
        const int kh = gi % 3;

        asm volatile("cp.async.wait_group 1;" ::: "memory");
        __syncthreads();
        if (gi > 0 && kh == 0) {
            issue_slab(cc);
            asm volatile("cp.async.commit_group;" ::: "memory");
            asm volatile("cp.async.wait_group 0;" ::: "memory");
            __syncthreads();
        }
        if (gi + 2 < NG) issue_Bgrp(gi + 2);
        asm volatile("cp.async.commit_group;" ::: "memory");

        const uint32_t* const Bg = smw + SM_B + (gi % 3) * B_GRP_WORDS;

        // ---- compute: 3 kw taps x 2 ksteps ----
        #pragma unroll
        for (int kw = 0; kw < 3; kw++) {
            const uint32_t abase = smem_base +
                (uint32_t)(((warp_m + kh) * 66 + kw) * SLAB_STRIDE) * 4 + a_thr_off;
            #pragma unroll
            for (int ks = 0; ks < 2; ks++) {
                uint32_t a[4][4];
                #pragma unroll
                for (int i = 0; i < 4; i++)
                    ldsm_x4(a[i], abase + i * (16 * SLAB_STRIDE * 4) + ks * 32);
                uint32_t b[4][2];
                const uint32_t* Brow =
                    Bg + kw * 2048 + ks * 1024 + (warp_n * 32 + g) * 8 + 2 * q;
                #pragma unroll
                for (int j = 0; j < 4; j++) {
                    const uint2 bb = *(const uint2*)(Brow + j * 64);
                    b[j][0] = bb.x; b[j][1] = bb.y;
                }
                #pragma unroll
                for (int i = 0; i < 4; i++)
                    #pragma unroll
                    for (int j = 0; j < 4; j++)
                        mma_f16(acc[i][j], a[i], b[j]);
            }
        }
    }

    // ---- epilogue: acc -> out[n][d][h][w] + bias ----
    const float bval = bias[0];
    const int h = h0 + warp_m;
    #pragma unroll
    for (int i = 0; i < 4; i++) {
        const int w0 = i * 16 + g;
        #pragma unroll
        for (int j = 0; j < 4; j++) {
            const int d = ny * ND + warp_n * 32 + j * 8 + 2 * q;
            float* p0 = out + (((size_t)n * D_OUT + d) * IMG + h) * IMG;
            float* p1 = p0 + (size_t)IMG * IMG;       // d+1
            p0[w0]     = acc[i][j][0] + bval;
            p1[w0]     = acc[i][j][1] + bval;
            p0[w0 + 8] = acc[i][j][2] + bval;
            p1[w0 + 8] = acc[i][j][3] + bval;
        }
    }
}

// ---------------------------------------------------------------------------
// Inputs (metadata order): x, core0, core1, core2, bias, [stride, pad]
// ---------------------------------------------------------------------------
extern "C" void kernel_launch(void* const* d_in, const int* in_sizes, int n_in,
                              void* d_out, int out_size) {
    const float* x     = (const float*)d_in[0];
    const float* core0 = (const float*)d_in[1];
    const float* core1 = (const float*)d_in[2];
    const float* core2 = (const float*)d_in[3];
    const float* bias  = (const float*)d_in[4];
    float* out = (float*)d_out;

    build_w_kernel<<<D_OUT, C_IN>>>(core0, core1, core2);
    prepack_x_kernel<<<dim3(32 * 4, IMG), 256>>>(x);

    const int smem_bytes = SM_TOTALW * 4;
    cudaFuncSetAttribute(conv_mma_kernel, cudaFuncAttributeMaxDynamicSharedMemorySize, smem_bytes);
    conv_mma_kernel<<<dim3(IMG / TH, 2, 32), 256, smem_bytes>>>(bias, out);
}